// round 1
// baseline (speedup 1.0000x reference)
#include <cuda_runtime.h>

#define BDIM 512

#define QR_PLANE   (64*66)          // 4224
#define QR_FLOATS  (10*QR_PLANE)    // 42240
#define V_FLOATS   (66*66)          // 4356
#define XS_FLOATS  (2*68*68)        // 9248 (overlaps qr region, phases 0-1 only)
#define WK_FLOATS  172
#define SMEM_FLOATS (QR_FLOATS + 2*V_FLOATS + WK_FLOATS)
#define SMEM_BYTES (SMEM_FLOATS*4)

__device__ float g_Kq[162];   // [q=3x3][c=2][s=3][u=3] composed 2-stage conv weights
__device__ float g_bq[9];     // per-offset bias (h_b folded through r_w)

__constant__ float c_qw[10][2][3][3];
__constant__ float c_qb[10];
__constant__ float c_fc[8][10];

// ---------------- setup: collapse 150-ch hidden conv into 9 composed 3x3 kernels ---
__global__ void vin_setup(const float* __restrict__ h_w,
                          const float* __restrict__ h_b,
                          const float* __restrict__ r_w)
{
    int t = threadIdx.x;
    if (t < 162) {
        int q = t / 18;
        int rest = t % 18;            // c*9 + s*3 + u
        float acc = 0.f;
        #pragma unroll 10
        for (int m = 0; m < 150; m++)
            acc += r_w[m*9 + q] * h_w[m*18 + rest];
        g_Kq[t] = acc;
    } else if (t < 171) {
        int q = t - 162;
        float acc = 0.f;
        #pragma unroll 10
        for (int m = 0; m < 150; m++)
            acc += r_w[m*9 + q] * h_b[m];
        g_bq[q] = acc;
    }
}

// ---------------- packed f32x2 helpers -------------------------------------------
__device__ __forceinline__ unsigned long long pk2(float lo, float hi){
    unsigned long long r;
    asm("mov.b64 %0, {%1, %2};" : "=l"(r) : "f"(lo), "f"(hi));
    return r;
}
__device__ __forceinline__ void upk2(unsigned long long v, float& lo, float& hi){
    asm("mov.b64 {%0, %1}, %2;" : "=f"(lo), "=f"(hi) : "l"(v));
}
__device__ __forceinline__ unsigned long long fma2(unsigned long long a,
                                                   unsigned long long b,
                                                   unsigned long long c){
    unsigned long long d;
    asm("fma.rn.f32x2 %0, %1, %2, %3;" : "=l"(d) : "l"(a), "l"(b), "l"(c));
    return d;
}

// ---------------- main: one CTA per image, whole VI loop in SMEM ------------------
__global__ void __launch_bounds__(BDIM, 1)
vin_main(const float* __restrict__ xg,
         const int*   __restrict__ pos_x,
         const int*   __restrict__ pos_y,
         const float* __restrict__ r_b,
         float*       __restrict__ out)
{
    extern __shared__ float smem[];
    float* qrS = smem;                    // 42240 floats, [a][row][col] stride 66
    float* vA  = smem + QR_FLOATS;        // 66x66 zero-ring padded (also rs in setup)
    float* vB  = vA + V_FLOATS;
    float* wK  = vB + V_FLOATS;           // composed weights (171)
    float* xsS = smem;                    // x tile 2x68x68 (pad 2), overlaps qrS

    const int b   = blockIdx.x;
    const int tid = threadIdx.x;
    const int row = tid >> 3;             // 0..63
    const int cg  = tid & 7;
    const int c0  = cg << 3;              // 8 pixels per thread, one row strip

    // ---- phase 0: zero pads, stage weights, load x --------------------------------
    for (int i = tid; i < XS_FLOATS; i += BDIM) xsS[i] = 0.f;
    for (int i = tid; i < V_FLOATS; i += BDIM) { vA[i] = 0.f; vB[i] = 0.f; }
    if (tid < 171) wK[tid] = (tid < 162) ? g_Kq[tid] : g_bq[tid - 162];
    __syncthreads();

    const float* xb = xg + (size_t)b * 8192;
    for (int i = tid; i < 8192; i += BDIM) {
        int c = i >> 12;
        int y = (i >> 6) & 63;
        int x = i & 63;
        xsS[c*4624 + (y+2)*68 + (x+2)] = xb[i];
    }
    __syncthreads();

    // ---- phase 1: r = composed(h_w,r_w) conv of x, exact boundary masking ---------
    {
        float racc[8];
        const float rb = r_b[0];
        #pragma unroll
        for (int p = 0; p < 8; p++) racc[p] = rb;
        #pragma unroll
        for (int q = 0; q < 9; q++) {
            const int qi = q / 3, qj = q % 3;
            const int yy = row + qi - 1;
            const bool rowok = (yy >= 0) && (yy < 64);
            float kw[18];
            #pragma unroll
            for (int t = 0; t < 18; t++) kw[t] = wK[q*18 + t];
            const float bqv = wK[162 + q];
            #pragma unroll
            for (int p = 0; p < 8; p++) {
                int xx = c0 + p + qj - 1;
                if (rowok && xx >= 0 && xx < 64) {
                    float t = bqv;
                    #pragma unroll
                    for (int c = 0; c < 2; c++)
                        #pragma unroll
                        for (int s = 0; s < 3; s++)
                            #pragma unroll
                            for (int u = 0; u < 3; u++)
                                t += kw[c*9 + s*3 + u] *
                                     xsS[c*4624 + (yy+s+1)*68 + (xx+u+1)];
                    racc[p] += t;
                }
            }
        }
        #pragma unroll
        for (int p = 0; p < 8; p++) vA[(row+1)*66 + c0 + p + 1] = racc[p];
    }
    __syncthreads();

    // ---- phase 2: loop-invariant qr = conv(r, q_w[:,0]) + q_b  (overwrites xs) ----
    {
        #pragma unroll
        for (int p = 0; p < 8; p++) {
            const int x = c0 + p;
            float win[9];
            #pragma unroll
            for (int s = 0; s < 3; s++)
                #pragma unroll
                for (int u = 0; u < 3; u++)
                    win[s*3+u] = vA[(row+s)*66 + x + u];
            #pragma unroll
            for (int a = 0; a < 10; a++) {
                float t = c_qb[a];
                #pragma unroll
                for (int s = 0; s < 3; s++)
                    #pragma unroll
                    for (int u = 0; u < 3; u++)
                        t += c_qw[a][0][s][u] * win[s*3+u];
                qrS[a*QR_PLANE + row*66 + x] = t;
            }
        }
    }
    __syncthreads();
    // clear vA (held r): v0 = 0
    for (int i = tid; i < V_FLOATS; i += BDIM) vA[i] = 0.f;
    __syncthreads();

    // ---- phase 3: K=50 value-iteration steps, all in SMEM, packed f32x2 -----------
    #pragma unroll 1
    for (int k = 0; k < 50; k++) {
        const float* vin  = (k & 1) ? vB : vA;
        float*       vout = (k & 1) ? vA : vB;

        const int base = row*66 + c0;
        float w0[10], w1[10], w2[10];
        #pragma unroll
        for (int i = 0; i < 10; i++) {
            w0[i] = vin[base + i];
            w1[i] = vin[base + 66 + i];
            w2[i] = vin[base + 132 + i];
        }
        unsigned long long pk[3][9];
        #pragma unroll
        for (int j = 0; j < 9; j++) {
            pk[0][j] = pk2(w0[j], w0[j+1]);
            pk[1][j] = pk2(w1[j], w1[j+1]);
            pk[2][j] = pk2(w2[j], w2[j+1]);
        }

        float vnew[8];
        #pragma unroll
        for (int a = 0; a < 10; a++) {
            unsigned long long acc[4];
            const int qb_ = a*QR_PLANE + base;
            #pragma unroll
            for (int p = 0; p < 4; p++)
                acc[p] = *reinterpret_cast<const unsigned long long*>(&qrS[qb_ + 2*p]);
            #pragma unroll
            for (int s = 0; s < 3; s++)
                #pragma unroll
                for (int u = 0; u < 3; u++) {
                    const float cw = c_qw[a][1][s][u];
                    const unsigned long long wd = pk2(cw, cw);
                    #pragma unroll
                    for (int p = 0; p < 4; p++)
                        acc[p] = fma2(pk[s][2*p + u], wd, acc[p]);
                }
            #pragma unroll
            for (int p = 0; p < 4; p++) {
                float lo, hi; upk2(acc[p], lo, hi);
                if (a == 0) { vnew[2*p] = lo; vnew[2*p+1] = hi; }
                else {
                    vnew[2*p]   = fmaxf(vnew[2*p], lo);
                    vnew[2*p+1] = fmaxf(vnew[2*p+1], hi);
                }
            }
        }
        const int ob = (row+1)*66 + c0 + 1;
        #pragma unroll
        for (int px = 0; px < 8; px++) vout[ob + px] = vnew[px];
        __syncthreads();
    }
    // after 50 iters (last wrote vA), final q only needed at (pos_x,pos_y)

    const int prow = pos_x[b];
    const int pcol = pos_y[b];
    if (row == prow && (pcol >> 3) == cg) {
        float win[9];
        #pragma unroll
        for (int s = 0; s < 3; s++)
            #pragma unroll
            for (int u = 0; u < 3; u++)
                win[s*3+u] = vA[(prow+s)*66 + pcol + u];
        float qv[10];
        #pragma unroll
        for (int a = 0; a < 10; a++) {
            float t = qrS[a*QR_PLANE + prow*66 + pcol];
            #pragma unroll
            for (int s = 0; s < 3; s++)
                #pragma unroll
                for (int u = 0; u < 3; u++)
                    t += c_qw[a][1][s][u] * win[s*3+u];
            qv[a] = t;
        }
        #pragma unroll
        for (int j = 0; j < 8; j++) {
            float o = 0.f;
            #pragma unroll
            for (int a = 0; a < 10; a++) o += qv[a] * c_fc[j][a];
            out[b*8 + j] = o;
        }
    }
}

// ---------------- launch ----------------------------------------------------------
extern "C" void kernel_launch(void* const* d_in, const int* in_sizes, int n_in,
                              void* d_out, int out_size)
{
    const float* x     = (const float*)d_in[0];
    const int*   pos_x = (const int*)  d_in[1];
    const int*   pos_y = (const int*)  d_in[2];
    const float* h_w   = (const float*)d_in[3];
    const float* h_b   = (const float*)d_in[4];
    const float* r_w   = (const float*)d_in[5];
    const float* r_b   = (const float*)d_in[6];
    const float* q_w   = (const float*)d_in[7];
    const float* q_b   = (const float*)d_in[8];
    const float* fc_w  = (const float*)d_in[9];

    (void)in_sizes; (void)n_in; (void)out_size;

    cudaFuncSetAttribute(vin_main, cudaFuncAttributeMaxDynamicSharedMemorySize,
                         SMEM_BYTES);

    cudaMemcpyToSymbolAsync(c_qw, q_w, 180*sizeof(float), 0,
                            cudaMemcpyDeviceToDevice, 0);
    cudaMemcpyToSymbolAsync(c_qb, q_b, 10*sizeof(float), 0,
                            cudaMemcpyDeviceToDevice, 0);
    cudaMemcpyToSymbolAsync(c_fc, fc_w, 80*sizeof(float), 0,
                            cudaMemcpyDeviceToDevice, 0);

    vin_setup<<<1, 192>>>(h_w, h_b, r_w);
    vin_main<<<128, BDIM, SMEM_BYTES>>>(x, pos_x, pos_y, r_b, (float*)d_out);
}